// round 1
// baseline (speedup 1.0000x reference)
#include <cuda_runtime.h>
#include <cstdint>
#include <cstddef>

#define C_   32
#define H_   192
#define W_   256
#define S_   9
#define N_   9
#define G_   8
#define HW_  (H_*W_)          // 49152
#define PIX  128              // pixels per block
#define NTHR 128
#define TILE_F  (PIX*S_)      // 1152 floats per channel sub-tile
#define TILE_F4 (TILE_F/4)    // 288 float4
#define MACRO_F4 (4*TILE_F4)  // 1152 float4 per 4-channel macro tile

__device__ float g_M[C_*C_];  // Wp^T Wp
__device__ float g_v[C_];     // Wp^T bp

__global__ void gcfs_setup(const float* __restrict__ Wp, const float* __restrict__ bp) {
    int t = threadIdx.x;
    for (int e = t; e < C_*C_; e += blockDim.x) {
        int i = e >> 5, j = e & 31;
        float m = 0.f;
        #pragma unroll
        for (int d = 0; d < C_; d++) m += Wp[d*C_ + i] * Wp[d*C_ + j];
        g_M[e] = m;
    }
    if (t < C_) {
        float v = 0.f;
        #pragma unroll
        for (int d = 0; d < C_; d++) v += bp[d] * Wp[d*C_ + t];
        g_v[t] = v;
    }
}

__device__ __forceinline__ void cp16(void* smem, const void* g) {
    uint32_t sa = (uint32_t)__cvta_generic_to_shared(smem);
    asm volatile("cp.async.cg.shared.global [%0], [%1], 16;\n" :: "r"(sa), "l"(g) : "memory");
}
__device__ __forceinline__ void cp_commit() {
    asm volatile("cp.async.commit_group;\n" ::: "memory");
}
template<int NW> __device__ __forceinline__ void cp_wait() {
    asm volatile("cp.async.wait_group %0;\n" :: "n"(NW) : "memory");
}

__global__ __launch_bounds__(NTHR)
void gcfs_main(const float* __restrict__ f, float* __restrict__ out) {
    __shared__ float  sM[C_*C_];
    __shared__ float  sv[C_];
    __shared__ float4 sbuf[2][MACRO_F4];   // 2 x 18432 B double buffer

    const int tid  = threadIdx.x;
    const int pix0 = blockIdx.x * PIX;
    const int p    = pix0 + tid;

    for (int e = tid; e < C_*C_; e += NTHR) sM[e] = g_M[e];
    if (tid < C_) sv[tid] = g_v[tid];

    // stage one macro tile: channels [cbase, cbase+4) of image n, 128 pixels x 9 s
    auto stage = [&](int n, int cbase, float4* dst) {
        #pragma unroll
        for (int k = 0; k < 9; k++) {
            int idx = tid + k*NTHR;              // 0..1151
            int sub = idx / TILE_F4;             // which channel (0..3)
            int off = idx - sub*TILE_F4;         // float4 within channel tile
            const float* gsrc = f + ((size_t)(n*C_ + cbase + sub)*HW_ + pix0)*S_ + (size_t)off*4;
            cp16(dst + idx, gsrc);
        }
        cp_commit();
    };

    // center-tap reference vector r_mid (prefetches the ref lines into L2 too)
    float rm[C_];
    #pragma unroll
    for (int c = 0; c < C_; c++)
        rm[c] = __ldg(f + ((size_t)c*HW_ + p)*S_ + (S_/2));

    float logit[S_];
    #pragma unroll
    for (int s = 0; s < S_; s++) logit[s] = 0.f;

    __syncthreads();  // sM/sv visible

    // ---------------- Phase 1: logits over ref (8 macro tiles) ----------------
    stage(0, 0, sbuf[0]);
    for (int k = 0; k < 8; k++) {
        if (k + 1 < 8) { stage(0, 4*(k+1), sbuf[(k+1)&1]); cp_wait<1>(); }
        else           { cp_wait<0>(); }
        __syncthreads();
        const float* tile = (const float*)sbuf[k&1];
        #pragma unroll
        for (int c4 = 0; c4 < 4; c4++) {
            int c = 4*k + c4;
            float t = sv[c];
            #pragma unroll
            for (int d = 0; d < C_; d++)
                t = fmaf(rm[d], sM[d*C_ + c], t);   // M symmetric; broadcast smem reads
            const float* row = tile + c4*TILE_F + tid*S_;
            #pragma unroll
            for (int s = 0; s < S_; s++)
                logit[s] = fmaf(t, row[s], logit[s]);
        }
        __syncthreads();
    }

    // ---------------- bridge: prefetch first phase-2 tile, do softmax ----------------
    stage(0, 0, sbuf[0]);   // phase-2 tile j=0 = ref group 0

    const float scale = 0.17677669529663689f;   // 1/sqrt(32)
    float att[S_];
    float mx = -1e30f;
    #pragma unroll
    for (int s = 0; s < S_; s++) { logit[s] *= scale; mx = fmaxf(mx, logit[s]); }
    float sum = 0.f;
    #pragma unroll
    for (int s = 0; s < S_; s++) { att[s] = __expf(logit[s] - mx); sum += att[s]; }
    float invs = 1.0f / sum;
    #pragma unroll
    for (int s = 0; s < S_; s++) att[s] *= invs;

    // ---------------- Phase 2: group correlations (72 macro tiles) ----------------
    // tile j: g = j/9, r = j%9 ; r==0 -> ref group g ; r>0 -> src image n=r, group g
    float refg[4][S_];
    for (int j = 0; j < 72; j++) {
        int g = j / 9, r = j - 9*g;
        if (j + 1 < 72) {
            int j2 = j + 1, g2 = j2 / 9, r2 = j2 - 9*g2;
            stage((r2 == 0) ? 0 : r2, 4*g2, sbuf[j2&1]);
            cp_wait<1>();
        } else {
            cp_wait<0>();
        }
        __syncthreads();
        const float* tile = (const float*)sbuf[j&1];
        if (r == 0) {
            #pragma unroll
            for (int c4 = 0; c4 < 4; c4++)
                #pragma unroll
                for (int s = 0; s < S_; s++)
                    refg[c4][s] = tile[c4*TILE_F + tid*S_ + s];
        } else {
            float acc[S_];
            #pragma unroll
            for (int s = 0; s < S_; s++) acc[s] = 0.f;
            #pragma unroll
            for (int c4 = 0; c4 < 4; c4++) {
                const float* row = tile + c4*TILE_F + tid*S_;
                #pragma unroll
                for (int s = 0; s < S_; s++)
                    acc[s] = fmaf(refg[c4][s], row[s], acc[s]);
            }
            float o = 0.f;
            #pragma unroll
            for (int s = 0; s < S_; s++) o = fmaf(acc[s], att[s], o);
            out[(size_t)((r-1)*G_ + g)*HW_ + p] = o;
        }
        __syncthreads();
    }
}

extern "C" void kernel_launch(void* const* d_in, const int* in_sizes, int n_in,
                              void* d_out, int out_size) {
    const float* f  = (const float*)d_in[0];
    const float* Wp = (const float*)d_in[1];
    const float* bp = (const float*)d_in[2];
    // d_in[3]=o, d_in[4]=G (fixed: 2, 8) — shapes hardcoded

    gcfs_setup<<<1, 256>>>(Wp, bp);
    gcfs_main<<<HW_/PIX, NTHR>>>(f, (float*)d_out);
}